// round 14
// baseline (speedup 1.0000x reference)
#include <cuda_runtime.h>

#define NB    5
#define BATCH 512
#define NPG   62
#define NNODES (BATCH*NPG)      /* 31744 */
#define FIN   5
#define NH    8
#define NC    3
#define EG    992               /* edges per graph */
#define NE    (BATCH*EG)        /* 507904 edges per band */
#define NEDG  (EG+NPG)          /* 1054 incl self loops */
#define DED   930
#define KCH   117               /* ceil(930/8) k-chunks of 8 */

/* ---------------- device scratch (no allocations allowed) ---------------- */
__device__ float g_stats[NB][10];                 /* zero-init; re-zeroed by k_attn */
__device__ __align__(16) float g_xcat[BATCH*15];
__device__ __align__(16) float g_Q[BATCH*64];
__device__ __align__(16) float g_Kt[64*BATCH];    /* transposed K */
__device__ __align__(16) float g_V[BATCH*64];
__device__ __align__(16) unsigned char g_srcl[(size_t)NB*BATCH*1056]; /* CSR src */
__device__ int g_excl[NB*BATCH*64];               /* CSR offsets */

/* == K1: fused QKV-GEMM (0..191) + BN stats (192..311) + edge sort (rest) = */
struct GemmSmem {
    float sN[8][948];                              /* normalized A rows, padded */
    union {
        float sW[8][8][64];                        /* [split][kk][col]   */
        float sAcc[8][8][68];                      /* [split][row][col]  */
    } u;
};
struct SortSmem {
    unsigned short s_tmp[NEDG];
    __align__(16) unsigned char s_srcl[1056];
    int s_cntw[16][64];
    int s_excl[64];
};

__global__ __launch_bounds__(512) void k_fused(
    const float* __restrict__ de,  const float* __restrict__ lng,
    const float* __restrict__ lnb,
    const float* __restrict__ qW,  const float* __restrict__ qb,
    const float* __restrict__ kW,  const float* __restrict__ kb,
    const float* __restrict__ vW,  const float* __restrict__ vb,
    const float* __restrict__ x,   const int* __restrict__ ei)
{
    __shared__ union { GemmSmem g; SortSmem s; float red[16][10]; } S;
    int bid = blockIdx.x;
    int t = threadIdx.x, w = t >> 5, lane = t & 31;

    if (bid < 192) {
        /* ---------------- QKV GEMM with inline LayerNorm ---------------- */
        int mat = bid / 64, tile = bid % 64;
        int row0 = tile * 8;
        const float* Wm = (mat == 0) ? qW : (mat == 1) ? kW : vW;
        const float* bm = (mat == 0) ? qb : (mat == 1) ? kb : vb;

        /* LN: warp per row (warps 0..7) */
        if (w < 8) {
            const float* dr = de + (size_t)(row0 + w) * DED;
            float v[30];
            float ssum = 0.f, ssq = 0.f;
            #pragma unroll
            for (int i = 0; i < 30; i++) {
                int j = lane + i*32;
                float z = (j < DED) ? dr[j] : 0.f;
                v[i] = z; ssum += z; ssq += z*z;
            }
            #pragma unroll
            for (int o = 16; o > 0; o >>= 1) {
                ssum += __shfl_xor_sync(0xffffffffu, ssum, o);
                ssq  += __shfl_xor_sync(0xffffffffu, ssq, o);
            }
            float mu   = ssum * (1.f/DED);
            float rstd = rsqrtf(ssq * (1.f/DED) - mu*mu + 1e-5f);
            #pragma unroll
            for (int i = 0; i < 30; i++) {
                int j = lane + i*32;
                if (j < DED) S.g.sN[w][j] = (v[i] - mu) * rstd * lng[j] + lnb[j];
            }
            for (int j = DED + lane; j < 948; j += 32) S.g.sN[w][j] = 0.f;
        }
        __syncthreads();

        int s  = t >> 6;          /* split 0..7 (64-thread group)   */
        int u  = t & 63;
        int rg = u >> 4;          /* rows rg*2, rg*2+1              */
        int cg = u & 15;          /* cols cg*4 .. +3                */

        float a0c0=0.f,a0c1=0.f,a0c2=0.f,a0c3=0.f;
        float a1c0=0.f,a1c1=0.f,a1c2=0.f,a1c3=0.f;

        float4 p0, p1;
        {
            int k0 = s * 8;
            int kA = k0 + rg, kB = k0 + rg + 4;
            p0 = (kA < DED) ? *(const float4*)(Wm + (size_t)kA*64 + cg*4)
                            : make_float4(0.f,0.f,0.f,0.f);
            p1 = (kB < DED) ? *(const float4*)(Wm + (size_t)kB*64 + cg*4)
                            : make_float4(0.f,0.f,0.f,0.f);
        }
        for (int kc = s; kc < KCH; kc += 8) {
            int k0 = kc * 8;
            *(float4*)&S.g.u.sW[s][rg  ][cg*4] = p0;
            *(float4*)&S.g.u.sW[s][rg+4][cg*4] = p1;
            asm volatile("bar.sync %0, 64;" :: "r"(s+1) : "memory");
            if (kc + 8 < KCH) {       /* prefetch next chunk, overlaps FMAs */
                int kn = (kc + 8) * 8;
                int kA = kn + rg, kB = kn + rg + 4;
                p0 = (kA < DED) ? *(const float4*)(Wm + (size_t)kA*64 + cg*4)
                                : make_float4(0.f,0.f,0.f,0.f);
                p1 = (kB < DED) ? *(const float4*)(Wm + (size_t)kB*64 + cg*4)
                                : make_float4(0.f,0.f,0.f,0.f);
            }
            #pragma unroll
            for (int kk = 0; kk < 8; kk++) {
                float a0 = S.g.sN[rg*2  ][k0+kk];
                float a1 = S.g.sN[rg*2+1][k0+kk];
                float4 wv = *(const float4*)&S.g.u.sW[s][kk][cg*4];
                a0c0 += a0*wv.x; a0c1 += a0*wv.y; a0c2 += a0*wv.z; a0c3 += a0*wv.w;
                a1c0 += a1*wv.x; a1c1 += a1*wv.y; a1c2 += a1*wv.z; a1c3 += a1*wv.w;
            }
            asm volatile("bar.sync %0, 64;" :: "r"(s+1) : "memory");
        }
        __syncthreads();                 /* sW region reused as sAcc */
        *(float4*)&S.g.u.sAcc[s][rg*2  ][cg*4] = make_float4(a0c0,a0c1,a0c2,a0c3);
        *(float4*)&S.g.u.sAcc[s][rg*2+1][cg*4] = make_float4(a1c0,a1c1,a1c2,a1c3);
        __syncthreads();

        int r = t >> 6, c = t & 63;
        float v = bm[c];
        #pragma unroll
        for (int ss = 0; ss < 8; ss++) v += S.g.u.sAcc[ss][r][c];
        if (mat == 1) g_Kt[(size_t)c * BATCH + row0 + r] = v;
        else {
            float* dst = (mat == 0) ? g_Q : g_V;
            dst[(size_t)(row0 + r) * 64 + c] = v;
        }
    } else if (bid < 312) {
        /* ---------------- BN statistics (120 blocks) -------------------- */
        int idx = bid - 192;
        int band = idx / 24, slice = idx % 24;
        const float* xb = x + (size_t)band * NNODES * FIN;
        float sm[5] = {0,0,0,0,0}, q[5] = {0,0,0,0,0};
        for (int n = slice * 512 + t; n < NNODES; n += 24 * 512) {
            const float* p = xb + (size_t)n * FIN;
            #pragma unroll
            for (int f = 0; f < 5; f++) { float v = p[f]; sm[f] += v; q[f] += v*v; }
        }
        #pragma unroll
        for (int o = 16; o > 0; o >>= 1) {
            #pragma unroll
            for (int f = 0; f < 5; f++) {
                sm[f] += __shfl_xor_sync(0xffffffffu, sm[f], o);
                q[f]  += __shfl_xor_sync(0xffffffffu, q[f],  o);
            }
        }
        if (lane == 0) {
            #pragma unroll
            for (int f = 0; f < 5; f++) { S.red[w][f] = sm[f]; S.red[w][5+f] = q[f]; }
        }
        __syncthreads();
        if (t < 10) {
            float acc = 0.f;
            #pragma unroll
            for (int i = 0; i < 16; i++) acc += S.red[i][t];
            atomicAdd(&g_stats[band][t], acc);
        }
    } else {
        /* ---------------- edge sort → CSR (2560 blocks) ----------------- */
        int idx = bid - 312;
        int band = idx / BATCH, b = idx % BATCH;
        for (int i = t; i < 16*64; i += 512) ((int*)S.s.s_cntw)[i] = 0;
        __syncthreads();
        const int* sp = ei + (size_t)band * 2 * NE + (size_t)b * EG;
        const int* dp = sp + NE;
        int base = b * NPG;
        for (int e = t; e < NEDG; e += 512) {
            int ls, ld;
            if (e < EG) { ls = sp[e] - base; ld = dp[e] - base; }
            else        { ls = ld = e - EG; }                 /* self loops */
            S.s.s_tmp[e] = (unsigned short)(ls | (ld << 8));
            atomicAdd(&S.s.s_cntw[w][ld], 1);
        }
        __syncthreads();
        if (w == 0) {     /* per-warp base conversion + scan, one warp */
            int c0 = 0, c1 = 0;
            #pragma unroll
            for (int ww = 0; ww < 16; ww++) {
                int t0 = S.s.s_cntw[ww][lane];    S.s.s_cntw[ww][lane]    = c0; c0 += t0;
                int t1 = S.s.s_cntw[ww][lane+32]; S.s.s_cntw[ww][lane+32] = c1; c1 += t1;
            }
            int v0 = c0, v1 = c1;
            #pragma unroll
            for (int o = 1; o < 32; o <<= 1) {
                int n0 = __shfl_up_sync(0xffffffffu, v0, o);
                int n1 = __shfl_up_sync(0xffffffffu, v1, o);
                if (lane >= o) { v0 += n0; v1 += n1; }
            }
            v1 += __shfl_sync(0xffffffffu, v0, 31);
            S.s.s_excl[lane]      = v0 - c0;
            S.s.s_excl[lane + 32] = v1 - c1;
        }
        __syncthreads();
        for (int e = t; e < NEDG; e += 512) {
            unsigned u = S.s.s_tmp[e];
            int ld = u >> 8;
            int p = S.s.s_excl[ld] + atomicAdd(&S.s.s_cntw[w][ld], 1);
            S.s.s_srcl[p] = (unsigned char)(u & 0xFF);
        }
        __syncthreads();
        size_t ob = (size_t)(band * BATCH + b);
        if (t < 66)
            ((uint4*)(g_srcl + ob*1056))[t] = ((const uint4*)S.s.s_srcl)[t];
        else if (t < 130)
            g_excl[ob*64 + (t - 66)] = S.s.s_excl[t - 66];
    }
}

/* == K2: GAT (CSR precomputed), 1024 thr, 2-way split gather ============= */
__global__ __launch_bounds__(1024) void k_gat(
    const float* __restrict__ x,
    const float* __restrict__ W, const float* __restrict__ asrc,
    const float* __restrict__ adst, const float* __restrict__ gbias,
    const float* __restrict__ bng, const float* __restrict__ bnb)
{
    int b = blockIdx.x, band = blockIdx.y;
    int t = threadIdx.x;

    __shared__ float s_xn[NPG][FIN];                 /* raw x */
    __shared__ __align__(16) float s_xt[NPG*NH*4];   /* [l][h]{x0,x1,x2,als'} */
    __shared__ float s_ald[NPG*NH];
    __shared__ __align__(16) unsigned char s_srcl[1056];
    __shared__ int s_excl[65];
    __shared__ float s_Wp[FIN*24], s_shW[24], s_as[24], s_ad[24], s_bias[NC];
    __shared__ float s_no[NPG*4];
    __shared__ float s_pool[NC];

    /* -------- phase 0: CSR + params (BN folded into weights) + raw x ---- */
    size_t ob = (size_t)(band * BATCH + b);
    if (t < 66) {
        ((uint4*)s_srcl)[t] = ((const uint4*)(g_srcl + ob*1056))[t];
    } else if (t < 131) {
        int d = t - 66;
        s_excl[d] = (d < 64) ? g_excl[ob*64 + d] : NEDG;
    } else if (t < 155) {
        int k = t - 131;
        float sh = 0.f;
        #pragma unroll
        for (int f = 0; f < FIN; f++) {
            float mean = g_stats[band][f] * (1.f/NNODES);
            float var  = g_stats[band][5+f] * (1.f/NNODES) - mean*mean;
            float sc   = rsqrtf(var + 1e-5f) * bng[band*5+f];
            float shf  = bnb[band*5+f] - mean*sc;
            float wv   = W[band*120 + f*24 + k];
            s_Wp[f*24 + k] = wv * sc;
            sh += wv * shf;
        }
        s_shW[k] = sh;
    }
    else if (t < 179) s_as[t-155] = asrc[band*24 + (t-155)];
    else if (t < 203) s_ad[t-179] = adst[band*24 + (t-179)];
    else if (t < 206) { s_bias[t-203] = gbias[band*3 + (t-203)]; s_pool[t-203] = 0.f; }
    else if (t < 516) {                              /* 310 threads: raw x */
        int i = t - 206;
        int l = i / FIN, f = i % FIN;
        s_xn[l][f] = x[(size_t)band * NNODES * FIN + (size_t)(b*NPG + l) * FIN + f];
    }
    if (t < NPG*4) s_no[t] = 0.f;
    __syncthreads();

    /* -------- phase 1: xt = (x*sc+sh) @ W via folded weights ------------ */
    for (int idx = t; idx < NPG * 24; idx += 1024) {
        int l = idx / 24, k = idx % 24;
        float acc = s_shW[k]
                  + s_xn[l][0]*s_Wp[k]    + s_xn[l][1]*s_Wp[24+k]
                  + s_xn[l][2]*s_Wp[48+k] + s_xn[l][3]*s_Wp[72+k]
                  + s_xn[l][4]*s_Wp[96+k];
        int h = k / 3, c = k % 3;
        s_xt[l*32 + h*4 + c] = acc;
    }
    __syncthreads();

    /* -------- phase 2: logits, pre-scaled by log2(e) -------------------- */
    if (t < NPG * NH) {
        const float LOG2E = 1.44269504f;
        int l = t >> 3, h = t & 7;
        const float* xp = &s_xt[l*32 + h*4];
        float x0 = xp[0], x1 = xp[1], x2 = xp[2];
        s_xt[l*32 + h*4 + 3] = (x0*s_as[h*3] + x1*s_as[h*3+1] + x2*s_as[h*3+2]) * LOG2E;
        s_ald[t]             = (x0*s_ad[h*3] + x1*s_ad[h*3+1] + x2*s_ad[h*3+2]) * LOG2E;
    }
    __syncthreads();

    /* -------- phase 3: gather, 2 threads per (dst, head) ---------------- */
    if (t < NPG * NH * 2) {
        int d = t >> 4, h = (t >> 1) & 7, half = t & 1;
        int beg = s_excl[d], end = s_excl[d+1];
        float ald = s_ald[d*8 + h];
        float den = 0.f, a0 = 0.f, a1 = 0.f, a2 = 0.f;
        #pragma unroll 2
        for (int e = beg + half; e < end; e += 2) {
            int ls = s_srcl[e];
            const float4 xv = *(const float4*)&s_xt[ls*32 + h*4];  /* x0,x1,x2,als' */
            float ev = xv.w + ald;
            ev = fmaxf(ev, 0.2f * ev);                 /* leaky 0.2 (scale commutes) */
            float wgt = exp2f(ev);                     /* pre-scaled by log2e */
            den += wgt; a0 += wgt*xv.x; a1 += wgt*xv.y; a2 += wgt*xv.z;
        }
        den += __shfl_xor_sync(0xffffffffu, den, 1);
        a0  += __shfl_xor_sync(0xffffffffu, a0, 1);
        a1  += __shfl_xor_sync(0xffffffffu, a1, 1);
        a2  += __shfl_xor_sync(0xffffffffu, a2, 1);
        if (half == 0) {
            float inv = 0.125f / den;                  /* /denom then head-mean */
            atomicAdd(&s_no[d*4+0], a0*inv);
            atomicAdd(&s_no[d*4+1], a1*inv);
            atomicAdd(&s_no[d*4+2], a2*inv);
        }
    }
    __syncthreads();

    /* -------- phase 4: bias + elu + graph mean-pool --------------------- */
    if (t < NPG * NC) {
        int d = t / 3, c = t % 3;
        float v = s_no[d*4+c] + s_bias[c];
        v = v > 0.f ? v : expm1f(v);
        atomicAdd(&s_pool[c], v);
    }
    __syncthreads();
    if (t < NC) g_xcat[b*15 + band*3 + t] = s_pool[t] * (1.f/62.f);
}

/* == K3: fg-FC + 512x512 attention + final FC + elu (4 rows, 512 thr) ==== */
__global__ __launch_bounds__(512) void k_attn(
    float* __restrict__ out, const float* __restrict__ faW,
    const float* __restrict__ fab, const float* __restrict__ fgW,
    const float* __restrict__ fgb)
{
    __shared__ float s_q[4*64], s_xo[4*64], s_sc[4*512], s_de[4*64];
    __shared__ __align__(16) float s_vt[64][68];     /* V tile, pad 68 */
    __shared__ float s_part[16][4];
    __shared__ float s_inv[4];
    int t = threadIdx.x, rowbase = blockIdx.x * 4;

    /* phase A: fg FC + Q load; idle threads of block 0 reset g_stats */
    if (t < 256) {
        int r = t >> 6, c = t & 63;
        float acc = fgb[c];
        #pragma unroll
        for (int i = 0; i < 15; i++)
            acc += g_xcat[(rowbase+r)*15 + i] * fgW[i*64 + c];
        s_xo[t] = acc > 0.f ? acc : expm1f(acc);
        s_q[t]  = g_Q[(rowbase+r)*64 + c];
    } else if (blockIdx.x == 0 && t < 256 + NB*10) {
        ((float*)g_stats)[t - 256] = 0.f;            /* replay-safe reset */
    }
    __syncthreads();

    /* phase B: scores, one column j per thread, 8-wide load batching */
    float ps[4];
    {
        int j = t;
        float acc[4] = {0.f, 0.f, 0.f, 0.f};
        for (int cb = 0; cb < 64; cb += 8) {
            float kv[8];
            #pragma unroll
            for (int i = 0; i < 8; i++) kv[i] = g_Kt[(cb+i)*BATCH + j];
            #pragma unroll
            for (int i = 0; i < 8; i++) {
                #pragma unroll
                for (int r = 0; r < 4; r++) acc[r] += s_q[r*64 + cb + i] * kv[i];
            }
        }
        #pragma unroll
        for (int r = 0; r < 4; r++) {
            float p = __expf(acc[r] * 0.125f);
            s_sc[r*512 + j] = p;
            ps[r] = p;
        }
    }
    #pragma unroll
    for (int o = 16; o > 0; o >>= 1) {
        #pragma unroll
        for (int r = 0; r < 4; r++) ps[r] += __shfl_xor_sync(0xffffffffu, ps[r], o);
    }
    { int w = t >> 5, lane = t & 31;
      if (lane == 0) { s_part[w][0]=ps[0]; s_part[w][1]=ps[1]; s_part[w][2]=ps[2]; s_part[w][3]=ps[3]; } }
    __syncthreads();
    if (t < 4) {
        float s = 0.f;
        #pragma unroll
        for (int w = 0; w < 16; w++) s += s_part[w][t];
        s_inv[t] = 1.f / s;
    }
    __syncthreads();

    /* phase C: PV via smem V tiles; thread = (r, cg, js), 8-way j-split */
    {
        int r = t >> 7, cg = (t >> 3) & 15, js = t & 7;
        float ax = 0.f, ay = 0.f, az = 0.f, aw = 0.f;
        for (int jt = 0; jt < 8; jt++) {
            int j0 = jt * 64;
            #pragma unroll
            for (int kk = 0; kk < 2; kk++) {
                int idx = t + kk*512;
                int jr = idx >> 4, c4 = idx & 15;
                *(float4*)&s_vt[jr][c4*4] =
                    *(const float4*)&g_V[(size_t)(j0+jr)*64 + c4*4];
            }
            __syncthreads();
            #pragma unroll
            for (int jj = 0; jj < 8; jj++) {
                int jl = jj*8 + js;
                float p = s_sc[r*512 + j0 + jl];
                float4 vv = *(const float4*)&s_vt[jl][cg*4];
                ax += p*vv.x; ay += p*vv.y; az += p*vv.z; aw += p*vv.w;
            }
            __syncthreads();
        }
        #pragma unroll
        for (int o = 1; o <= 4; o <<= 1) {
            ax += __shfl_xor_sync(0xffffffffu, ax, o);
            ay += __shfl_xor_sync(0xffffffffu, ay, o);
            az += __shfl_xor_sync(0xffffffffu, az, o);
            aw += __shfl_xor_sync(0xffffffffu, aw, o);
        }
        if (js == 0) {
            float inv = s_inv[r];
            s_de[r*64 + cg*4 + 0] = ax * inv;
            s_de[r*64 + cg*4 + 1] = ay * inv;
            s_de[r*64 + cg*4 + 2] = az * inv;
            s_de[r*64 + cg*4 + 3] = aw * inv;
        }
    }
    __syncthreads();

    /* phase D: final FC + elu */
    if (t < 12) {
        int r = t / 3, c = t % 3;
        float acc = fab[c];
        #pragma unroll 8
        for (int i = 0; i < 64; i++) {
            acc += s_xo[r*64 + i] * faW[i*3 + c];
            acc += s_de[r*64 + i] * faW[(64+i)*3 + c];
        }
        acc = acc > 0.f ? acc : expm1f(acc);
        out[(rowbase+r)*3 + c] = acc;
    }
}

/* ============================== launcher ================================ */
extern "C" void kernel_launch(void* const* d_in, const int* in_sizes, int n_in,
                              void* d_out, int out_size)
{
    const float* x     = (const float*)d_in[0];
    const int*   ei    = (const int*)  d_in[1];
    const float* de    = (const float*)d_in[3];
    const float* bng   = (const float*)d_in[4];
    const float* bnb   = (const float*)d_in[5];
    const float* W     = (const float*)d_in[6];
    const float* asrc  = (const float*)d_in[7];
    const float* adst  = (const float*)d_in[8];
    const float* gbias = (const float*)d_in[9];
    const float* fgW   = (const float*)d_in[10];
    const float* fgb   = (const float*)d_in[11];
    const float* lng   = (const float*)d_in[12];
    const float* lnb   = (const float*)d_in[13];
    const float* qW    = (const float*)d_in[14];
    const float* qb    = (const float*)d_in[15];
    const float* kW    = (const float*)d_in[16];
    const float* kb    = (const float*)d_in[17];
    const float* vW    = (const float*)d_in[18];
    const float* vb    = (const float*)d_in[19];
    const float* faW   = (const float*)d_in[20];
    const float* fab   = (const float*)d_in[21];
    float* out = (float*)d_out;

    /* strictly sequential, default stream — capture-safe */
    k_fused<<<312 + NB*BATCH, 512>>>(de, lng, lnb, qW, qb, kW, kb, vW, vb, x, ei);
    k_gat<<<dim3(BATCH, NB), 1024>>>(x, W, asrc, adst, gbias, bng, bnb);
    k_attn<<<128, 512>>>(out, faW, fab, fgW, fgb);
}

// round 15
// speedup vs baseline: 1.2131x; 1.2131x over previous
#include <cuda_runtime.h>

#define NB    5
#define BATCH 512
#define NPG   62
#define NNODES (BATCH*NPG)      /* 31744 */
#define FIN   5
#define NH    8
#define NC    3
#define EG    992               /* edges per graph */
#define NE    (BATCH*EG)        /* 507904 edges per band */
#define NEDG  (EG+NPG)          /* 1054 incl self loops */
#define DED   930
#define KCH   117               /* ceil(930/8) k-chunks of 8 */

/* ---------------- device scratch (no allocations allowed) ---------------- */
__device__ float g_stats[NB][10];                 /* zero-init; re-zeroed by k_attn */
__device__ __align__(16) float g_xcat[BATCH*15];
__device__ __align__(16) float g_Q[BATCH*64];
__device__ __align__(16) float g_Kt[64*BATCH];    /* transposed K */
__device__ __align__(16) float g_V[BATCH*64];
__device__ __align__(16) unsigned char g_srcl[(size_t)NB*BATCH*1056]; /* CSR src */
__device__ int g_excl[NB*BATCH*64];               /* CSR offsets */

/* = K1: QKV-GEMM 4-row tiles (0..383) + BN stats (384..503) + edge sort == */
struct GemmSmem {
    float sN[4][948];                              /* normalized A rows, padded */
    union {
        float sW[8][8][64];                        /* [split][kk][col]   */
        float sAcc[8][4][68];                      /* [split][row][col]  */
    } u;
};
struct SortSmem {
    unsigned short s_tmp[NEDG];
    __align__(16) unsigned char s_srcl[1056];
    int s_cntw[16][64];
    int s_excl[64];
};

__global__ __launch_bounds__(512) void k_fused(
    const float* __restrict__ de,  const float* __restrict__ lng,
    const float* __restrict__ lnb,
    const float* __restrict__ qW,  const float* __restrict__ qb,
    const float* __restrict__ kW,  const float* __restrict__ kb,
    const float* __restrict__ vW,  const float* __restrict__ vb,
    const float* __restrict__ x,   const int* __restrict__ ei)
{
    __shared__ union { GemmSmem g; SortSmem s; float red[16][10]; } S;
    int bid = blockIdx.x;
    int t = threadIdx.x, w = t >> 5, lane = t & 31;

    if (bid < 384) {
        /* -------- QKV GEMM, 4-row tiles, inline LayerNorm --------------- */
        int mat = bid / 128, tile = bid % 128;
        int row0 = tile * 4;
        const float* Wm = (mat == 0) ? qW : (mat == 1) ? kW : vW;
        const float* bm = (mat == 0) ? qb : (mat == 1) ? kb : vb;

        /* LN: warp per row (warps 0..3) */
        if (w < 4) {
            const float* dr = de + (size_t)(row0 + w) * DED;
            float v[30];
            float ssum = 0.f, ssq = 0.f;
            #pragma unroll
            for (int i = 0; i < 30; i++) {
                int j = lane + i*32;
                float z = (j < DED) ? dr[j] : 0.f;
                v[i] = z; ssum += z; ssq += z*z;
            }
            #pragma unroll
            for (int o = 16; o > 0; o >>= 1) {
                ssum += __shfl_xor_sync(0xffffffffu, ssum, o);
                ssq  += __shfl_xor_sync(0xffffffffu, ssq, o);
            }
            float mu   = ssum * (1.f/DED);
            float rstd = rsqrtf(ssq * (1.f/DED) - mu*mu + 1e-5f);
            #pragma unroll
            for (int i = 0; i < 30; i++) {
                int j = lane + i*32;
                if (j < DED) S.g.sN[w][j] = (v[i] - mu) * rstd * lng[j] + lnb[j];
            }
            for (int j = DED + lane; j < 948; j += 32) S.g.sN[w][j] = 0.f;
        }
        __syncthreads();

        int s  = t >> 6;          /* split 0..7 (64-thread group)   */
        int u  = t & 63;
        int rg = u >> 4;          /* row rg (0..3)                  */
        int cg = u & 15;          /* cols cg*4 .. +3                */

        float c0 = 0.f, c1 = 0.f, c2 = 0.f, c3 = 0.f;

        float4 p0, p1;
        {
            int k0 = s * 8;
            int kA = k0 + rg, kB = k0 + rg + 4;
            p0 = (kA < DED) ? *(const float4*)(Wm + (size_t)kA*64 + cg*4)
                            : make_float4(0.f,0.f,0.f,0.f);
            p1 = (kB < DED) ? *(const float4*)(Wm + (size_t)kB*64 + cg*4)
                            : make_float4(0.f,0.f,0.f,0.f);
        }
        for (int kc = s; kc < KCH; kc += 8) {
            int k0 = kc * 8;
            *(float4*)&S.g.u.sW[s][rg  ][cg*4] = p0;
            *(float4*)&S.g.u.sW[s][rg+4][cg*4] = p1;
            asm volatile("bar.sync %0, 64;" :: "r"(s+1) : "memory");
            if (kc + 8 < KCH) {       /* prefetch next chunk, overlaps FMAs */
                int kn = (kc + 8) * 8;
                int kA = kn + rg, kB = kn + rg + 4;
                p0 = (kA < DED) ? *(const float4*)(Wm + (size_t)kA*64 + cg*4)
                                : make_float4(0.f,0.f,0.f,0.f);
                p1 = (kB < DED) ? *(const float4*)(Wm + (size_t)kB*64 + cg*4)
                                : make_float4(0.f,0.f,0.f,0.f);
            }
            #pragma unroll
            for (int kk = 0; kk < 8; kk++) {
                float a = S.g.sN[rg][k0+kk];
                float4 wv = *(const float4*)&S.g.u.sW[s][kk][cg*4];
                c0 += a*wv.x; c1 += a*wv.y; c2 += a*wv.z; c3 += a*wv.w;
            }
            asm volatile("bar.sync %0, 64;" :: "r"(s+1) : "memory");
        }
        __syncthreads();                 /* sW region reused as sAcc */
        *(float4*)&S.g.u.sAcc[s][rg][cg*4] = make_float4(c0, c1, c2, c3);
        __syncthreads();

        if (t < 256) {
            int r = t >> 6, c = t & 63;
            float v = bm[c];
            #pragma unroll
            for (int ss = 0; ss < 8; ss++) v += S.g.u.sAcc[ss][r][c];
            if (mat == 1) g_Kt[(size_t)c * BATCH + row0 + r] = v;
            else {
                float* dst = (mat == 0) ? g_Q : g_V;
                dst[(size_t)(row0 + r) * 64 + c] = v;
            }
        }
    } else if (bid < 504) {
        /* ---------------- BN statistics (120 blocks) -------------------- */
        int idx = bid - 384;
        int band = idx / 24, slice = idx % 24;
        const float* xb = x + (size_t)band * NNODES * FIN;
        float sm[5] = {0,0,0,0,0}, q[5] = {0,0,0,0,0};
        for (int n = slice * 512 + t; n < NNODES; n += 24 * 512) {
            const float* p = xb + (size_t)n * FIN;
            #pragma unroll
            for (int f = 0; f < 5; f++) { float v = p[f]; sm[f] += v; q[f] += v*v; }
        }
        #pragma unroll
        for (int o = 16; o > 0; o >>= 1) {
            #pragma unroll
            for (int f = 0; f < 5; f++) {
                sm[f] += __shfl_xor_sync(0xffffffffu, sm[f], o);
                q[f]  += __shfl_xor_sync(0xffffffffu, q[f],  o);
            }
        }
        if (lane == 0) {
            #pragma unroll
            for (int f = 0; f < 5; f++) { S.red[w][f] = sm[f]; S.red[w][5+f] = q[f]; }
        }
        __syncthreads();
        if (t < 10) {
            float acc = 0.f;
            #pragma unroll
            for (int i = 0; i < 16; i++) acc += S.red[i][t];
            atomicAdd(&g_stats[band][t], acc);
        }
    } else {
        /* ---------------- edge sort → CSR (2560 blocks) ----------------- */
        int idx = bid - 504;
        int band = idx / BATCH, b = idx % BATCH;
        for (int i = t; i < 16*64; i += 512) ((int*)S.s.s_cntw)[i] = 0;
        __syncthreads();
        const int* sp = ei + (size_t)band * 2 * NE + (size_t)b * EG;
        const int* dp = sp + NE;
        int base = b * NPG;
        for (int e = t; e < NEDG; e += 512) {
            int ls, ld;
            if (e < EG) { ls = sp[e] - base; ld = dp[e] - base; }
            else        { ls = ld = e - EG; }                 /* self loops */
            S.s.s_tmp[e] = (unsigned short)(ls | (ld << 8));
            atomicAdd(&S.s.s_cntw[w][ld], 1);
        }
        __syncthreads();
        if (w == 0) {     /* per-warp base conversion + scan, one warp */
            int c0 = 0, c1 = 0;
            #pragma unroll
            for (int ww = 0; ww < 16; ww++) {
                int t0 = S.s.s_cntw[ww][lane];    S.s.s_cntw[ww][lane]    = c0; c0 += t0;
                int t1 = S.s.s_cntw[ww][lane+32]; S.s.s_cntw[ww][lane+32] = c1; c1 += t1;
            }
            int v0 = c0, v1 = c1;
            #pragma unroll
            for (int o = 1; o < 32; o <<= 1) {
                int n0 = __shfl_up_sync(0xffffffffu, v0, o);
                int n1 = __shfl_up_sync(0xffffffffu, v1, o);
                if (lane >= o) { v0 += n0; v1 += n1; }
            }
            v1 += __shfl_sync(0xffffffffu, v0, 31);
            S.s.s_excl[lane]      = v0 - c0;
            S.s.s_excl[lane + 32] = v1 - c1;
        }
        __syncthreads();
        for (int e = t; e < NEDG; e += 512) {
            unsigned u = S.s.s_tmp[e];
            int ld = u >> 8;
            int p = S.s.s_excl[ld] + atomicAdd(&S.s.s_cntw[w][ld], 1);
            S.s.s_srcl[p] = (unsigned char)(u & 0xFF);
        }
        __syncthreads();
        size_t ob = (size_t)(band * BATCH + b);
        if (t < 66)
            ((uint4*)(g_srcl + ob*1056))[t] = ((const uint4*)S.s.s_srcl)[t];
        else if (t < 130)
            g_excl[ob*64 + (t - 66)] = S.s.s_excl[t - 66];
    }
}

/* ====== K2: per-(band,graph) GAT + pooling (CSR precomputed) ============ */
__global__ __launch_bounds__(512) void k_gat(
    const float* __restrict__ x,
    const float* __restrict__ W, const float* __restrict__ asrc,
    const float* __restrict__ adst, const float* __restrict__ gbias,
    const float* __restrict__ bng, const float* __restrict__ bnb)
{
    int b = blockIdx.x, band = blockIdx.y;
    int t = threadIdx.x;

    __shared__ float s_xn[NPG][FIN];                 /* raw x */
    __shared__ __align__(16) float s_xt[NPG*NH*4];   /* [l][h]{x0,x1,x2,als'} */
    __shared__ float s_ald[NPG*NH];
    __shared__ __align__(16) unsigned char s_srcl[1056];
    __shared__ int s_excl[65];
    __shared__ float s_Wp[FIN*24], s_shW[24], s_as[24], s_ad[24], s_bias[NC];
    __shared__ float s_no[NPG*4];
    __shared__ float s_pool[NC];

    /* -------- phase 0: CSR + params (BN folded into weights) + raw x ---- */
    size_t ob = (size_t)(band * BATCH + b);
    if (t < 66) {
        ((uint4*)s_srcl)[t] = ((const uint4*)(g_srcl + ob*1056))[t];
    } else if (t < 131) {
        int d = t - 66;
        s_excl[d] = (d < 64) ? g_excl[ob*64 + d] : NEDG;
    } else if (t < 155) {
        int k = t - 131;
        float sh = 0.f;
        #pragma unroll
        for (int f = 0; f < FIN; f++) {
            float mean = g_stats[band][f] * (1.f/NNODES);
            float var  = g_stats[band][5+f] * (1.f/NNODES) - mean*mean;
            float sc   = rsqrtf(var + 1e-5f) * bng[band*5+f];
            float shf  = bnb[band*5+f] - mean*sc;
            float wv   = W[band*120 + f*24 + k];
            s_Wp[f*24 + k] = wv * sc;
            sh += wv * shf;
        }
        s_shW[k] = sh;
    }
    else if (t < 179) s_as[t-155] = asrc[band*24 + (t-155)];
    else if (t < 203) s_ad[t-179] = adst[band*24 + (t-179)];
    else if (t < 206) { s_bias[t-203] = gbias[band*3 + (t-203)]; s_pool[t-203] = 0.f; }
    if (t < NPG*4) s_no[t] = 0.f;
    if (t >= 202) {                                  /* 310 threads: raw x */
        int i = t - 202;
        int l = i / FIN, f = i % FIN;
        s_xn[l][f] = x[(size_t)band * NNODES * FIN + (size_t)(b*NPG + l) * FIN + f];
    }
    __syncthreads();

    /* -------- phase 1: xt = (x*sc+sh) @ W via folded weights ------------ */
    for (int idx = t; idx < NPG * 24; idx += 512) {
        int l = idx / 24, k = idx % 24;
        float acc = s_shW[k]
                  + s_xn[l][0]*s_Wp[k]    + s_xn[l][1]*s_Wp[24+k]
                  + s_xn[l][2]*s_Wp[48+k] + s_xn[l][3]*s_Wp[72+k]
                  + s_xn[l][4]*s_Wp[96+k];
        int h = k / 3, c = k % 3;
        s_xt[l*32 + h*4 + c] = acc;
    }
    __syncthreads();

    /* -------- phase 2: logits, pre-scaled by log2(e) -------------------- */
    if (t < NPG * NH) {
        const float LOG2E = 1.44269504f;
        int l = t >> 3, h = t & 7;
        const float* xp = &s_xt[l*32 + h*4];
        float x0 = xp[0], x1 = xp[1], x2 = xp[2];
        s_xt[l*32 + h*4 + 3] = (x0*s_as[h*3] + x1*s_as[h*3+1] + x2*s_as[h*3+2]) * LOG2E;
        s_ald[t]             = (x0*s_ad[h*3] + x1*s_ad[h*3+1] + x2*s_ad[h*3+2]) * LOG2E;
    }
    __syncthreads();

    /* -------- phase 3: atomic-free gather per (dst, head) --------------- */
    if (t < NPG * NH) {
        int d = t >> 3, h = t & 7;
        int beg = s_excl[d], end = s_excl[d+1];
        float ald = s_ald[t];
        float den = 0.f, a0 = 0.f, a1 = 0.f, a2 = 0.f;
        #pragma unroll 2
        for (int e = beg; e < end; e++) {
            int ls = s_srcl[e];
            const float4 xv = *(const float4*)&s_xt[ls*32 + h*4];  /* x0,x1,x2,als' */
            float ev = xv.w + ald;
            ev = fmaxf(ev, 0.2f * ev);                 /* leaky 0.2 (scale commutes) */
            float wgt = exp2f(ev);                     /* pre-scaled by log2e */
            den += wgt; a0 += wgt*xv.x; a1 += wgt*xv.y; a2 += wgt*xv.z;
        }
        float inv = 0.125f / den;                      /* /denom then head-mean */
        atomicAdd(&s_no[d*4+0], a0*inv);
        atomicAdd(&s_no[d*4+1], a1*inv);
        atomicAdd(&s_no[d*4+2], a2*inv);
    }
    __syncthreads();

    /* -------- phase 4: bias + elu + graph mean-pool --------------------- */
    if (t < NPG * NC) {
        int d = t / 3, c = t % 3;
        float v = s_no[d*4+c] + s_bias[c];
        v = v > 0.f ? v : expm1f(v);
        atomicAdd(&s_pool[c], v);
    }
    __syncthreads();
    if (t < NC) g_xcat[b*15 + band*3 + t] = s_pool[t] * (1.f/62.f);
}

/* == K3: fg-FC + 512x512 attention + final FC + elu (4 rows, 512 thr) ==== */
__global__ __launch_bounds__(512) void k_attn(
    float* __restrict__ out, const float* __restrict__ faW,
    const float* __restrict__ fab, const float* __restrict__ fgW,
    const float* __restrict__ fgb)
{
    __shared__ float s_q[4*64], s_xo[4*64], s_sc[4*512], s_de[4*64];
    __shared__ __align__(16) float s_vt[64][68];     /* V tile, pad 68 */
    __shared__ float s_part[16][4];
    __shared__ float s_inv[4];
    int t = threadIdx.x, rowbase = blockIdx.x * 4;

    /* phase A: fg FC + Q load; idle threads of block 0 reset g_stats */
    if (t < 256) {
        int r = t >> 6, c = t & 63;
        float acc = fgb[c];
        #pragma unroll
        for (int i = 0; i < 15; i++)
            acc += g_xcat[(rowbase+r)*15 + i] * fgW[i*64 + c];
        s_xo[t] = acc > 0.f ? acc : expm1f(acc);
        s_q[t]  = g_Q[(rowbase+r)*64 + c];
    } else if (blockIdx.x == 0 && t < 256 + NB*10) {
        ((float*)g_stats)[t - 256] = 0.f;            /* replay-safe reset */
    }
    __syncthreads();

    /* phase B: scores, one column j per thread, 8-wide load batching */
    float ps[4];
    {
        int j = t;
        float acc[4] = {0.f, 0.f, 0.f, 0.f};
        for (int cb = 0; cb < 64; cb += 8) {
            float kv[8];
            #pragma unroll
            for (int i = 0; i < 8; i++) kv[i] = g_Kt[(cb+i)*BATCH + j];
            #pragma unroll
            for (int i = 0; i < 8; i++) {
                #pragma unroll
                for (int r = 0; r < 4; r++) acc[r] += s_q[r*64 + cb + i] * kv[i];
            }
        }
        #pragma unroll
        for (int r = 0; r < 4; r++) {
            float p = __expf(acc[r] * 0.125f);
            s_sc[r*512 + j] = p;
            ps[r] = p;
        }
    }
    #pragma unroll
    for (int o = 16; o > 0; o >>= 1) {
        #pragma unroll
        for (int r = 0; r < 4; r++) ps[r] += __shfl_xor_sync(0xffffffffu, ps[r], o);
    }
    { int w = t >> 5, lane = t & 31;
      if (lane == 0) { s_part[w][0]=ps[0]; s_part[w][1]=ps[1]; s_part[w][2]=ps[2]; s_part[w][3]=ps[3]; } }
    __syncthreads();
    if (t < 4) {
        float s = 0.f;
        #pragma unroll
        for (int w = 0; w < 16; w++) s += s_part[w][t];
        s_inv[t] = 1.f / s;
    }
    __syncthreads();

    /* phase C: PV via smem V tiles; thread = (r, cg, js), 8-way j-split */
    {
        int r = t >> 7, cg = (t >> 3) & 15, js = t & 7;
        float ax = 0.f, ay = 0.f, az = 0.f, aw = 0.f;
        for (int jt = 0; jt < 8; jt++) {
            int j0 = jt * 64;
            #pragma unroll
            for (int kk = 0; kk < 2; kk++) {
                int idx = t + kk*512;
                int jr = idx >> 4, c4 = idx & 15;
                *(float4*)&s_vt[jr][c4*4] =
                    *(const float4*)&g_V[(size_t)(j0+jr)*64 + c4*4];
            }
            __syncthreads();
            #pragma unroll
            for (int jj = 0; jj < 8; jj++) {
                int jl = jj*8 + js;
                float p = s_sc[r*512 + j0 + jl];
                float4 vv = *(const float4*)&s_vt[jl][cg*4];
                ax += p*vv.x; ay += p*vv.y; az += p*vv.z; aw += p*vv.w;
            }
            __syncthreads();
        }
        #pragma unroll
        for (int o = 1; o <= 4; o <<= 1) {
            ax += __shfl_xor_sync(0xffffffffu, ax, o);
            ay += __shfl_xor_sync(0xffffffffu, ay, o);
            az += __shfl_xor_sync(0xffffffffu, az, o);
            aw += __shfl_xor_sync(0xffffffffu, aw, o);
        }
        if (js == 0) {
            float inv = s_inv[r];
            s_de[r*64 + cg*4 + 0] = ax * inv;
            s_de[r*64 + cg*4 + 1] = ay * inv;
            s_de[r*64 + cg*4 + 2] = az * inv;
            s_de[r*64 + cg*4 + 3] = aw * inv;
        }
    }
    __syncthreads();

    /* phase D: final FC + elu */
    if (t < 12) {
        int r = t / 3, c = t % 3;
        float acc = fab[c];
        #pragma unroll 8
        for (int i = 0; i < 64; i++) {
            acc += s_xo[r*64 + i] * faW[i*3 + c];
            acc += s_de[r*64 + i] * faW[(64+i)*3 + c];
        }
        acc = acc > 0.f ? acc : expm1f(acc);
        out[(rowbase+r)*3 + c] = acc;
    }
}

/* ============================== launcher ================================ */
extern "C" void kernel_launch(void* const* d_in, const int* in_sizes, int n_in,
                              void* d_out, int out_size)
{
    const float* x     = (const float*)d_in[0];
    const int*   ei    = (const int*)  d_in[1];
    const float* de    = (const float*)d_in[3];
    const float* bng   = (const float*)d_in[4];
    const float* bnb   = (const float*)d_in[5];
    const float* W     = (const float*)d_in[6];
    const float* asrc  = (const float*)d_in[7];
    const float* adst  = (const float*)d_in[8];
    const float* gbias = (const float*)d_in[9];
    const float* fgW   = (const float*)d_in[10];
    const float* fgb   = (const float*)d_in[11];
    const float* lng   = (const float*)d_in[12];
    const float* lnb   = (const float*)d_in[13];
    const float* qW    = (const float*)d_in[14];
    const float* qb    = (const float*)d_in[15];
    const float* kW    = (const float*)d_in[16];
    const float* kb    = (const float*)d_in[17];
    const float* vW    = (const float*)d_in[18];
    const float* vb    = (const float*)d_in[19];
    const float* faW   = (const float*)d_in[20];
    const float* fab   = (const float*)d_in[21];
    float* out = (float*)d_out;

    /* strictly sequential, default stream — capture-safe */
    k_fused<<<504 + NB*BATCH, 512>>>(de, lng, lnb, qW, qb, kW, kb, vW, vb, x, ei);
    k_gat<<<dim3(BATCH, NB), 512>>>(x, W, asrc, adst, gbias, bng, bnb);
    k_attn<<<128, 512>>>(out, faW, fab, fgW, fgb);
}

// round 16
// speedup vs baseline: 1.3418x; 1.1061x over previous
#include <cuda_runtime.h>

#define NB    5
#define BATCH 512
#define NPG   62
#define NNODES (BATCH*NPG)      /* 31744 */
#define FIN   5
#define NH    8
#define NC    3
#define EG    992               /* edges per graph */
#define NE    (BATCH*EG)        /* 507904 edges per band */
#define NEDG  (EG+NPG)          /* 1054 incl self loops */
#define DED   930
#define KCH   117               /* ceil(930/8) k-chunks of 8 */

/* ---------------- device scratch (no allocations allowed) ---------------- */
__device__ float g_stats[NB][10];                 /* zero-init; re-zeroed by k_attn */
__device__ __align__(16) float g_xcat[BATCH*15];
__device__ __align__(16) float g_Q[BATCH*64];
__device__ __align__(16) float g_Kt[64*BATCH];    /* transposed K */
__device__ __align__(16) float g_V[BATCH*64];
__device__ __align__(16) unsigned char g_srcl[(size_t)NB*BATCH*1056]; /* CSR src */
__device__ int g_excl[NB*BATCH*64];               /* CSR offsets */

/* == K1: fused QKV-GEMM (0..191) + BN stats (192..311) + edge sort (rest) = */
struct GemmSmem {
    float sN[8][948];                              /* normalized A rows, padded */
    union {
        float sW[8][8][64];                        /* [split][kk][col]   */
        float sAcc[8][8][68];                      /* [split][row][col]  */
    } u;
};
struct SortSmem {
    unsigned short s_tmp[NEDG];
    __align__(16) unsigned char s_srcl[1056];
    int s_cntw[16][64];
    int s_excl[64];
};

__global__ __launch_bounds__(512) void k_fused(
    const float* __restrict__ de,  const float* __restrict__ lng,
    const float* __restrict__ lnb,
    const float* __restrict__ qW,  const float* __restrict__ qb,
    const float* __restrict__ kW,  const float* __restrict__ kb,
    const float* __restrict__ vW,  const float* __restrict__ vb,
    const float* __restrict__ x,   const int* __restrict__ ei)
{
    __shared__ union { GemmSmem g; SortSmem s; float red[16][10]; } S;
    int bid = blockIdx.x;
    int t = threadIdx.x, w = t >> 5, lane = t & 31;

    if (bid < 192) {
        /* ---------------- QKV GEMM with inline LayerNorm ---------------- */
        int mat = bid / 64, tile = bid % 64;
        int row0 = tile * 8;
        const float* Wm = (mat == 0) ? qW : (mat == 1) ? kW : vW;
        const float* bm = (mat == 0) ? qb : (mat == 1) ? kb : vb;

        /* LN: warp per row (warps 0..7) */
        if (w < 8) {
            const float* dr = de + (size_t)(row0 + w) * DED;
            float v[30];
            float ssum = 0.f, ssq = 0.f;
            #pragma unroll
            for (int i = 0; i < 30; i++) {
                int j = lane + i*32;
                float z = (j < DED) ? dr[j] : 0.f;
                v[i] = z; ssum += z; ssq += z*z;
            }
            #pragma unroll
            for (int o = 16; o > 0; o >>= 1) {
                ssum += __shfl_xor_sync(0xffffffffu, ssum, o);
                ssq  += __shfl_xor_sync(0xffffffffu, ssq, o);
            }
            float mu   = ssum * (1.f/DED);
            float rstd = rsqrtf(ssq * (1.f/DED) - mu*mu + 1e-5f);
            #pragma unroll
            for (int i = 0; i < 30; i++) {
                int j = lane + i*32;
                if (j < DED) S.g.sN[w][j] = (v[i] - mu) * rstd * lng[j] + lnb[j];
            }
            for (int j = DED + lane; j < 948; j += 32) S.g.sN[w][j] = 0.f;
        }
        __syncthreads();

        int s  = t >> 6;          /* split 0..7 (64-thread group)   */
        int u  = t & 63;
        int rg = u >> 4;          /* rows rg*2, rg*2+1              */
        int cg = u & 15;          /* cols cg*4 .. +3                */

        float a0c0=0.f,a0c1=0.f,a0c2=0.f,a0c3=0.f;
        float a1c0=0.f,a1c1=0.f,a1c2=0.f,a1c3=0.f;

        float4 p0, p1;
        {
            int k0 = s * 8;
            int kA = k0 + rg, kB = k0 + rg + 4;
            p0 = (kA < DED) ? *(const float4*)(Wm + (size_t)kA*64 + cg*4)
                            : make_float4(0.f,0.f,0.f,0.f);
            p1 = (kB < DED) ? *(const float4*)(Wm + (size_t)kB*64 + cg*4)
                            : make_float4(0.f,0.f,0.f,0.f);
        }
        for (int kc = s; kc < KCH; kc += 8) {
            int k0 = kc * 8;
            *(float4*)&S.g.u.sW[s][rg  ][cg*4] = p0;
            *(float4*)&S.g.u.sW[s][rg+4][cg*4] = p1;
            asm volatile("bar.sync %0, 64;" :: "r"(s+1) : "memory");
            if (kc + 8 < KCH) {       /* prefetch next chunk, overlaps FMAs */
                int kn = (kc + 8) * 8;
                int kA = kn + rg, kB = kn + rg + 4;
                p0 = (kA < DED) ? *(const float4*)(Wm + (size_t)kA*64 + cg*4)
                                : make_float4(0.f,0.f,0.f,0.f);
                p1 = (kB < DED) ? *(const float4*)(Wm + (size_t)kB*64 + cg*4)
                                : make_float4(0.f,0.f,0.f,0.f);
            }
            #pragma unroll
            for (int kk = 0; kk < 8; kk++) {
                float a0 = S.g.sN[rg*2  ][k0+kk];
                float a1 = S.g.sN[rg*2+1][k0+kk];
                float4 wv = *(const float4*)&S.g.u.sW[s][kk][cg*4];
                a0c0 += a0*wv.x; a0c1 += a0*wv.y; a0c2 += a0*wv.z; a0c3 += a0*wv.w;
                a1c0 += a1*wv.x; a1c1 += a1*wv.y; a1c2 += a1*wv.z; a1c3 += a1*wv.w;
            }
            asm volatile("bar.sync %0, 64;" :: "r"(s+1) : "memory");
        }
        __syncthreads();                 /* sW region reused as sAcc */
        *(float4*)&S.g.u.sAcc[s][rg*2  ][cg*4] = make_float4(a0c0,a0c1,a0c2,a0c3);
        *(float4*)&S.g.u.sAcc[s][rg*2+1][cg*4] = make_float4(a1c0,a1c1,a1c2,a1c3);
        __syncthreads();

        int r = t >> 6, c = t & 63;
        float v = bm[c];
        #pragma unroll
        for (int ss = 0; ss < 8; ss++) v += S.g.u.sAcc[ss][r][c];
        if (mat == 1) g_Kt[(size_t)c * BATCH + row0 + r] = v;
        else {
            float* dst = (mat == 0) ? g_Q : g_V;
            dst[(size_t)(row0 + r) * 64 + c] = v;
        }
    } else if (bid < 312) {
        /* ---------------- BN statistics (120 blocks) -------------------- */
        int idx = bid - 192;
        int band = idx / 24, slice = idx % 24;
        const float* xb = x + (size_t)band * NNODES * FIN;
        float sm[5] = {0,0,0,0,0}, q[5] = {0,0,0,0,0};
        for (int n = slice * 512 + t; n < NNODES; n += 24 * 512) {
            const float* p = xb + (size_t)n * FIN;
            #pragma unroll
            for (int f = 0; f < 5; f++) { float v = p[f]; sm[f] += v; q[f] += v*v; }
        }
        #pragma unroll
        for (int o = 16; o > 0; o >>= 1) {
            #pragma unroll
            for (int f = 0; f < 5; f++) {
                sm[f] += __shfl_xor_sync(0xffffffffu, sm[f], o);
                q[f]  += __shfl_xor_sync(0xffffffffu, q[f],  o);
            }
        }
        if (lane == 0) {
            #pragma unroll
            for (int f = 0; f < 5; f++) { S.red[w][f] = sm[f]; S.red[w][5+f] = q[f]; }
        }
        __syncthreads();
        if (t < 10) {
            float acc = 0.f;
            #pragma unroll
            for (int i = 0; i < 16; i++) acc += S.red[i][t];
            atomicAdd(&g_stats[band][t], acc);
        }
    } else {
        /* ---------------- edge sort → CSR (2560 blocks) ----------------- */
        int idx = bid - 312;
        int band = idx / BATCH, b = idx % BATCH;
        for (int i = t; i < 16*64; i += 512) ((int*)S.s.s_cntw)[i] = 0;
        __syncthreads();
        const int* sp = ei + (size_t)band * 2 * NE + (size_t)b * EG;
        const int* dp = sp + NE;
        int base = b * NPG;
        for (int e = t; e < NEDG; e += 512) {
            int ls, ld;
            if (e < EG) { ls = sp[e] - base; ld = dp[e] - base; }
            else        { ls = ld = e - EG; }                 /* self loops */
            S.s.s_tmp[e] = (unsigned short)(ls | (ld << 8));
            atomicAdd(&S.s.s_cntw[w][ld], 1);
        }
        __syncthreads();
        if (w == 0) {     /* per-warp base conversion + scan, one warp */
            int c0 = 0, c1 = 0;
            #pragma unroll
            for (int ww = 0; ww < 16; ww++) {
                int t0 = S.s.s_cntw[ww][lane];    S.s.s_cntw[ww][lane]    = c0; c0 += t0;
                int t1 = S.s.s_cntw[ww][lane+32]; S.s.s_cntw[ww][lane+32] = c1; c1 += t1;
            }
            int v0 = c0, v1 = c1;
            #pragma unroll
            for (int o = 1; o < 32; o <<= 1) {
                int n0 = __shfl_up_sync(0xffffffffu, v0, o);
                int n1 = __shfl_up_sync(0xffffffffu, v1, o);
                if (lane >= o) { v0 += n0; v1 += n1; }
            }
            v1 += __shfl_sync(0xffffffffu, v0, 31);
            S.s.s_excl[lane]      = v0 - c0;
            S.s.s_excl[lane + 32] = v1 - c1;
        }
        __syncthreads();
        for (int e = t; e < NEDG; e += 512) {
            unsigned u = S.s.s_tmp[e];
            int ld = u >> 8;
            int p = S.s.s_excl[ld] + atomicAdd(&S.s.s_cntw[w][ld], 1);
            S.s.s_srcl[p] = (unsigned char)(u & 0xFF);
        }
        __syncthreads();
        size_t ob = (size_t)(band * BATCH + b);
        if (t < 66)
            ((uint4*)(g_srcl + ob*1056))[t] = ((const uint4*)S.s.s_srcl)[t];
        else if (t < 130)
            g_excl[ob*64 + (t - 66)] = S.s.s_excl[t - 66];
    }
}

/* ====== K2: per-(band,graph) GAT + pooling (CSR precomputed) ============ */
__global__ __launch_bounds__(512) void k_gat(
    const float* __restrict__ x,
    const float* __restrict__ W, const float* __restrict__ asrc,
    const float* __restrict__ adst, const float* __restrict__ gbias,
    const float* __restrict__ bng, const float* __restrict__ bnb)
{
    int b = blockIdx.x, band = blockIdx.y;
    int t = threadIdx.x;

    __shared__ float s_xn[NPG][FIN];                 /* raw x */
    __shared__ __align__(16) float s_xt[NPG*NH*4];   /* [l][h]{x0,x1,x2,als'} */
    __shared__ float s_ald[NPG*NH];
    __shared__ __align__(16) unsigned char s_srcl[1056];
    __shared__ int s_excl[65];
    __shared__ float s_Wp[FIN*24], s_shW[24], s_as[24], s_ad[24], s_bias[NC];
    __shared__ float s_no[NPG*4];
    __shared__ float s_pool[NC];

    /* -------- phase 0: CSR + params (BN folded into weights) + raw x ---- */
    size_t ob = (size_t)(band * BATCH + b);
    if (t < 66) {
        ((uint4*)s_srcl)[t] = ((const uint4*)(g_srcl + ob*1056))[t];
    } else if (t < 131) {
        int d = t - 66;
        s_excl[d] = (d < 64) ? g_excl[ob*64 + d] : NEDG;
    } else if (t < 155) {
        int k = t - 131;
        float sh = 0.f;
        #pragma unroll
        for (int f = 0; f < FIN; f++) {
            float mean = g_stats[band][f] * (1.f/NNODES);
            float var  = g_stats[band][5+f] * (1.f/NNODES) - mean*mean;
            float sc   = rsqrtf(var + 1e-5f) * bng[band*5+f];
            float shf  = bnb[band*5+f] - mean*sc;
            float wv   = W[band*120 + f*24 + k];
            s_Wp[f*24 + k] = wv * sc;
            sh += wv * shf;
        }
        s_shW[k] = sh;
    }
    else if (t < 179) s_as[t-155] = asrc[band*24 + (t-155)];
    else if (t < 203) s_ad[t-179] = adst[band*24 + (t-179)];
    else if (t < 206) { s_bias[t-203] = gbias[band*3 + (t-203)]; s_pool[t-203] = 0.f; }
    if (t < NPG*4) s_no[t] = 0.f;
    if (t >= 202) {                                  /* 310 threads: raw x */
        int i = t - 202;
        int l = i / FIN, f = i % FIN;
        s_xn[l][f] = x[(size_t)band * NNODES * FIN + (size_t)(b*NPG + l) * FIN + f];
    }
    __syncthreads();

    /* -------- phase 1: xt = (x*sc+sh) @ W via folded weights ------------ */
    for (int idx = t; idx < NPG * 24; idx += 512) {
        int l = idx / 24, k = idx % 24;
        float acc = s_shW[k]
                  + s_xn[l][0]*s_Wp[k]    + s_xn[l][1]*s_Wp[24+k]
                  + s_xn[l][2]*s_Wp[48+k] + s_xn[l][3]*s_Wp[72+k]
                  + s_xn[l][4]*s_Wp[96+k];
        int h = k / 3, c = k % 3;
        s_xt[l*32 + h*4 + c] = acc;
    }
    __syncthreads();

    /* -------- phase 2: logits, pre-scaled by log2(e) -------------------- */
    if (t < NPG * NH) {
        const float LOG2E = 1.44269504f;
        int l = t >> 3, h = t & 7;
        const float* xp = &s_xt[l*32 + h*4];
        float x0 = xp[0], x1 = xp[1], x2 = xp[2];
        s_xt[l*32 + h*4 + 3] = (x0*s_as[h*3] + x1*s_as[h*3+1] + x2*s_as[h*3+2]) * LOG2E;
        s_ald[t]             = (x0*s_ad[h*3] + x1*s_ad[h*3+1] + x2*s_ad[h*3+2]) * LOG2E;
    }
    __syncthreads();

    /* -------- phase 3: atomic-free gather per (dst, head) --------------- */
    if (t < NPG * NH) {
        int d = t >> 3, h = t & 7;
        int beg = s_excl[d], end = s_excl[d+1];
        float ald = s_ald[t];
        float den = 0.f, a0 = 0.f, a1 = 0.f, a2 = 0.f;
        #pragma unroll 2
        for (int e = beg; e < end; e++) {
            int ls = s_srcl[e];
            const float4 xv = *(const float4*)&s_xt[ls*32 + h*4];  /* x0,x1,x2,als' */
            float ev = xv.w + ald;
            ev = fmaxf(ev, 0.2f * ev);                 /* leaky 0.2 (scale commutes) */
            float wgt = exp2f(ev);                     /* pre-scaled by log2e */
            den += wgt; a0 += wgt*xv.x; a1 += wgt*xv.y; a2 += wgt*xv.z;
        }
        float inv = 0.125f / den;                      /* /denom then head-mean */
        atomicAdd(&s_no[d*4+0], a0*inv);
        atomicAdd(&s_no[d*4+1], a1*inv);
        atomicAdd(&s_no[d*4+2], a2*inv);
    }
    __syncthreads();

    /* -------- phase 4: bias + elu + graph mean-pool --------------------- */
    if (t < NPG * NC) {
        int d = t / 3, c = t % 3;
        float v = s_no[d*4+c] + s_bias[c];
        v = v > 0.f ? v : expm1f(v);
        atomicAdd(&s_pool[c], v);
    }
    __syncthreads();
    if (t < NC) g_xcat[b*15 + band*3 + t] = s_pool[t] * (1.f/62.f);
}

/* == K3: fg-FC + 512x512 attention + final FC + elu (4 rows, 512 thr) ==== */
__global__ __launch_bounds__(512) void k_attn(
    float* __restrict__ out, const float* __restrict__ faW,
    const float* __restrict__ fab, const float* __restrict__ fgW,
    const float* __restrict__ fgb)
{
    __shared__ float s_q[4*64], s_xo[4*64], s_sc[4*512], s_de[4*64];
    __shared__ __align__(16) float s_vt[64][68];     /* V tile, pad 68 */
    __shared__ float s_part[16][4];
    __shared__ float s_inv[4];
    int t = threadIdx.x, rowbase = blockIdx.x * 4;

    /* phase A: fg FC + Q load; idle threads of block 0 reset g_stats */
    if (t < 256) {
        int r = t >> 6, c = t & 63;
        float acc = fgb[c];
        #pragma unroll
        for (int i = 0; i < 15; i++)
            acc += g_xcat[(rowbase+r)*15 + i] * fgW[i*64 + c];
        s_xo[t] = acc > 0.f ? acc : expm1f(acc);
        s_q[t]  = g_Q[(rowbase+r)*64 + c];
    } else if (blockIdx.x == 0 && t < 256 + NB*10) {
        ((float*)g_stats)[t - 256] = 0.f;            /* replay-safe reset */
    }
    __syncthreads();

    /* phase B: scores, one column j per thread, 8-wide load batching */
    float ps[4];
    {
        int j = t;
        float acc[4] = {0.f, 0.f, 0.f, 0.f};
        for (int cb = 0; cb < 64; cb += 8) {
            float kv[8];
            #pragma unroll
            for (int i = 0; i < 8; i++) kv[i] = g_Kt[(cb+i)*BATCH + j];
            #pragma unroll
            for (int i = 0; i < 8; i++) {
                #pragma unroll
                for (int r = 0; r < 4; r++) acc[r] += s_q[r*64 + cb + i] * kv[i];
            }
        }
        #pragma unroll
        for (int r = 0; r < 4; r++) {
            float p = __expf(acc[r] * 0.125f);
            s_sc[r*512 + j] = p;
            ps[r] = p;
        }
    }
    #pragma unroll
    for (int o = 16; o > 0; o >>= 1) {
        #pragma unroll
        for (int r = 0; r < 4; r++) ps[r] += __shfl_xor_sync(0xffffffffu, ps[r], o);
    }
    { int w = t >> 5, lane = t & 31;
      if (lane == 0) { s_part[w][0]=ps[0]; s_part[w][1]=ps[1]; s_part[w][2]=ps[2]; s_part[w][3]=ps[3]; } }
    __syncthreads();
    if (t < 4) {
        float s = 0.f;
        #pragma unroll
        for (int w = 0; w < 16; w++) s += s_part[w][t];
        s_inv[t] = 1.f / s;
    }
    __syncthreads();

    /* phase C: PV via smem V tiles; thread = (r, cg, js), 8-way j-split */
    {
        int r = t >> 7, cg = (t >> 3) & 15, js = t & 7;
        float ax = 0.f, ay = 0.f, az = 0.f, aw = 0.f;
        for (int jt = 0; jt < 8; jt++) {
            int j0 = jt * 64;
            #pragma unroll
            for (int kk = 0; kk < 2; kk++) {
                int idx = t + kk*512;
                int jr = idx >> 4, c4 = idx & 15;
                *(float4*)&s_vt[jr][c4*4] =
                    *(const float4*)&g_V[(size_t)(j0+jr)*64 + c4*4];
            }
            __syncthreads();
            #pragma unroll
            for (int jj = 0; jj < 8; jj++) {
                int jl = jj*8 + js;
                float p = s_sc[r*512 + j0 + jl];
                float4 vv = *(const float4*)&s_vt[jl][cg*4];
                ax += p*vv.x; ay += p*vv.y; az += p*vv.z; aw += p*vv.w;
            }
            __syncthreads();
        }
        #pragma unroll
        for (int o = 1; o <= 4; o <<= 1) {
            ax += __shfl_xor_sync(0xffffffffu, ax, o);
            ay += __shfl_xor_sync(0xffffffffu, ay, o);
            az += __shfl_xor_sync(0xffffffffu, az, o);
            aw += __shfl_xor_sync(0xffffffffu, aw, o);
        }
        if (js == 0) {
            float inv = s_inv[r];
            s_de[r*64 + cg*4 + 0] = ax * inv;
            s_de[r*64 + cg*4 + 1] = ay * inv;
            s_de[r*64 + cg*4 + 2] = az * inv;
            s_de[r*64 + cg*4 + 3] = aw * inv;
        }
    }
    __syncthreads();

    /* phase D: final FC + elu */
    if (t < 12) {
        int r = t / 3, c = t % 3;
        float acc = fab[c];
        #pragma unroll 8
        for (int i = 0; i < 64; i++) {
            acc += s_xo[r*64 + i] * faW[i*3 + c];
            acc += s_de[r*64 + i] * faW[(64+i)*3 + c];
        }
        acc = acc > 0.f ? acc : expm1f(acc);
        out[(rowbase+r)*3 + c] = acc;
    }
}

/* ============================== launcher ================================ */
extern "C" void kernel_launch(void* const* d_in, const int* in_sizes, int n_in,
                              void* d_out, int out_size)
{
    const float* x     = (const float*)d_in[0];
    const int*   ei    = (const int*)  d_in[1];
    const float* de    = (const float*)d_in[3];
    const float* bng   = (const float*)d_in[4];
    const float* bnb   = (const float*)d_in[5];
    const float* W     = (const float*)d_in[6];
    const float* asrc  = (const float*)d_in[7];
    const float* adst  = (const float*)d_in[8];
    const float* gbias = (const float*)d_in[9];
    const float* fgW   = (const float*)d_in[10];
    const float* fgb   = (const float*)d_in[11];
    const float* lng   = (const float*)d_in[12];
    const float* lnb   = (const float*)d_in[13];
    const float* qW    = (const float*)d_in[14];
    const float* qb    = (const float*)d_in[15];
    const float* kW    = (const float*)d_in[16];
    const float* kb    = (const float*)d_in[17];
    const float* vW    = (const float*)d_in[18];
    const float* vb    = (const float*)d_in[19];
    const float* faW   = (const float*)d_in[20];
    const float* fab   = (const float*)d_in[21];
    float* out = (float*)d_out;

    /* strictly sequential, default stream — capture-safe */
    k_fused<<<312 + NB*BATCH, 512>>>(de, lng, lnb, qW, qb, kW, kb, vW, vb, x, ei);
    k_gat<<<dim3(BATCH, NB), 512>>>(x, W, asrc, adst, gbias, bng, bnb);
    k_attn<<<128, 512>>>(out, faW, fab, fgW, fgb);
}